// round 10
// baseline (speedup 1.0000x reference)
#include <cuda_runtime.h>
#include <cuda_bf16.h>
#include <cuda_fp16.h>
#include <math.h>
#include <stdint.h>

// Problem dims (fixed)
#define BB   2
#define SQ   512
#define SKK  512
#define EE   512
#define HH   256
#define MR   1024            // B*SQ = B*SK
#define NTOT (BB*SQ*SKK)     // 524288

// ---------------- scratch (device globals; no allocation allowed) -------------
__device__ float g_qf [MR*HH];
__device__ float g_kf [MR*HH];
__device__ float g_qp [MR*HH];
__device__ float g_vq [MR*HH];
__device__ float g_kpT[HH*MR];   // [H][B*SK]
__device__ float g_vkT[HH*MR];   // [H][B*SK]
// fp16 weight images: word layout [layer][k][nw] (nw = n/2, f16x2)
__device__ __align__(16) uint32_t g_Wh[2 * 256 * 128];

// SMEM map (byte offsets from 1024-aligned base)
#define SM_A   0u        // 64 rows x 512B  (fp16 A) = 32KB
#define SM_W   32768u    // 4 bufs x 16KB = 64KB
#define SM_VEC 98304u    // vectors + reductions (8KB)
#define SMEM_BYTES (106496 + 1024)

// ---------------- PTX helpers --------------------------------------------------
__device__ __forceinline__ uint32_t smem_u32(const void* p) {
    return (uint32_t)__cvta_generic_to_shared(p);
}
__device__ __forceinline__ void ldsm_x4(uint32_t (&r)[4], uint32_t addr) {
    asm volatile("ldmatrix.sync.aligned.m8n8.x4.shared.b16 {%0,%1,%2,%3}, [%4];"
        : "=r"(r[0]), "=r"(r[1]), "=r"(r[2]), "=r"(r[3]) : "r"(addr));
}
__device__ __forceinline__ void ldsm_x4_t(uint32_t (&r)[4], uint32_t addr) {
    asm volatile("ldmatrix.sync.aligned.m8n8.x4.trans.shared.b16 {%0,%1,%2,%3}, [%4];"
        : "=r"(r[0]), "=r"(r[1]), "=r"(r[2]), "=r"(r[3]) : "r"(addr));
}
__device__ __forceinline__ void mma_f16(float (&d)[4], const uint32_t (&a)[4],
                                        uint32_t b0, uint32_t b1) {
    asm volatile("mma.sync.aligned.m16n8k16.row.col.f32.f16.f16.f32 "
        "{%0,%1,%2,%3}, {%4,%5,%6,%7}, {%8,%9}, {%0,%1,%2,%3};"
        : "+f"(d[0]), "+f"(d[1]), "+f"(d[2]), "+f"(d[3])
        : "r"(a[0]), "r"(a[1]), "r"(a[2]), "r"(a[3]), "r"(b0), "r"(b1));
}
__device__ __forceinline__ unsigned long long pack_dup(float a) {
    unsigned long long r;
    asm("mov.b64 %0, {%1, %1};" : "=l"(r) : "f"(a));
    return r;
}
__device__ __forceinline__ void unpack2(unsigned long long v, float& lo, float& hi) {
    asm("mov.b64 {%0, %1}, %2;" : "=f"(lo), "=f"(hi) : "l"(v));
}
__device__ __forceinline__ void ffma2(unsigned long long& acc, unsigned long long a,
                                      unsigned long long b) {
    asm("fma.rn.f32x2 %0, %1, %2, %0;" : "+l"(acc) : "l"(a), "l"(b));
}

// ---------------- small math helpers ------------------------------------------
// pack two floats as f16x2 (v0 -> low half, v1 -> high half)
__device__ __forceinline__ uint32_t f16x2bits(float v0, float v1) {
    __half2 h = __floats2half2_rn(v0, v1);
    return *reinterpret_cast<uint32_t*>(&h);
}
__device__ __forceinline__ float softplusf(float x) {
    if (x > 20.f) return x;
    return log1pf(expf(x));
}

// ---------------- weight convert prologue (fp16) -------------------------------
__global__ __launch_bounds__(256)
void wsplit_kernel(const float* __restrict__ W2, const float* __restrict__ W3)
{
    int idx = blockIdx.x * 256 + threadIdx.x;     // 0..65535
    int layer = idx >> 15;
    int rem   = idx & 32767;
    int k  = rem >> 7;          // 0..255
    int nw = rem & 127;         // 0..127
    const float* W = layer ? W3 : W2;
    float v0 = W[k * 256 + nw * 2];
    float v1 = W[k * 256 + nw * 2 + 1];
    g_Wh[idx] = f16x2bits(v0, v1);
}

// ---------------- prologue: batched 1024x256 projection GEMM (f32x2) ----------
struct ProjJob {
    const float* A; const float* W; const float* bias; float* C;
    int wrow0; int doRelu; int doTrans;
};

__global__ __launch_bounds__(256)
void proj_batch_kernel(ProjJob j0, ProjJob j1, ProjJob j2, ProjJob j3, int K)
{
    ProjJob jb = (blockIdx.z == 0) ? j0 : (blockIdx.z == 1) ? j1 :
                 (blockIdx.z == 2) ? j2 : j3;
    __shared__ float As[16][36];
    __shared__ float Ws[16][68];
    const int tid = threadIdx.x;
    const int m0  = blockIdx.y * 32;
    const int n0  = blockIdx.x * 64;
    const int ty  = tid >> 4, tx = tid & 15;

    unsigned long long acc2[2][2] = {{0ull, 0ull}, {0ull, 0ull}};
    const int nch = K >> 4;
    for (int ch = 0; ch < nch; ch++) {
        const int kc = ch << 4;
        __syncthreads();
        {
            int e = tid;        int m = e >> 4, kk = e & 15;
            As[kk][m] = jb.A[(m0 + m) * K + kc + kk];
            e = tid + 256;      m = e >> 4;     kk = e & 15;
            As[kk][m] = jb.A[(m0 + m) * K + kc + kk];
        }
        #pragma unroll
        for (int i = 0; i < 4; i++) {
            int e = tid + (i << 8);
            int kk = e >> 6, n = e & 63;
            Ws[kk][n] = jb.W[(jb.wrow0 + kc + kk) * 256 + n0 + n];
        }
        __syncthreads();
        #pragma unroll
        for (int kk = 0; kk < 16; kk++) {
            unsigned long long a0d = pack_dup(As[kk][ty * 2]);
            unsigned long long a1d = pack_dup(As[kk][ty * 2 + 1]);
            unsigned long long w01 = *(const unsigned long long*)&Ws[kk][tx * 4];
            unsigned long long w23 = *(const unsigned long long*)&Ws[kk][tx * 4 + 2];
            ffma2(acc2[0][0], a0d, w01);
            ffma2(acc2[0][1], a0d, w23);
            ffma2(acc2[1][0], a1d, w01);
            ffma2(acc2[1][1], a1d, w23);
        }
    }
    #pragma unroll
    for (int i = 0; i < 2; i++) {
        float vout[4];
        unpack2(acc2[i][0], vout[0], vout[1]);
        unpack2(acc2[i][1], vout[2], vout[3]);
        const int r = m0 + ty * 2 + i;
        #pragma unroll
        for (int j = 0; j < 4; j++) {
            const int n = n0 + tx * 4 + j;
            float v = vout[j] + (jb.bias ? jb.bias[n] : 0.f);
            if (jb.doRelu) v = fmaxf(v, 0.f);
            if (jb.doTrans) jb.C[n * MR + r] = v;
            else            jb.C[r * 256 + n] = v;
        }
    }
}

// ---------------- main pairwise-MLP kernel (fp16 mma, 2 CTAs/SM) ---------------

// copy one 32-row k-chunk (16KB) into one of 4 smem buffers (256 threads)
__device__ __forceinline__ void cp_chunk(const char* __restrict__ srcH,
                                         uint32_t dstbase, int tid)
{
    #pragma unroll
    for (int i = 0; i < 4; i++) {
        int e = tid + i * 256;                 // 0..1023
        int k = e >> 5, u = e & 31;            // row, 16B unit
        uint32_t d = dstbase + (uint32_t)k * 512u + (uint32_t)((u ^ (k & 7)) << 4);
        asm volatile("cp.async.cg.shared.global [%0], [%1], 16;"
                     :: "r"(d), "l"(srcH + e * 16));
    }
    asm volatile("cp.async.commit_group;" ::: "memory");
}

// build 2 adjacent 16B units (g0, g0+1) of one A row: j0 = 8*g0 + quad*2
__device__ __forceinline__ void a_store_units(char* smp, int m, int quad, int g0,
                                              float v0, float v1, float v2, float v3)
{
    char* arow = smp + (uint32_t)m * 512u;
    uint32_t off0 = (uint32_t)(((g0 ^ (m & 7)) << 4) + quad * 4);
    *(uint32_t*)(arow + SM_A + off0) = f16x2bits(v0, v1);
    uint32_t off1 = (uint32_t)((((g0 + 1) ^ (m & 7)) << 4) + quad * 4);
    *(uint32_t*)(arow + SM_A + off1) = f16x2bits(v2, v3);
}

// One 64x256x256 fp16 GEMM: acc += A(smem) @ W(streamed, 4x16KB ring).
// Caller must have issued cp_chunk for chunks 0..2.
__device__ __forceinline__ void gemm_pass(uint32_t abase,
                                          const char* __restrict__ WhL,
                                          int warpM, int warpN, int lane, int tid,
                                          float (&acc)[2][8][4])
{
    const int rit  = (lane & 7) | (((lane >> 3) & 1) << 3); // row within 16-tile
    const int koff = lane >> 4;                              // 0/1: unit select
    uint32_t a_row[2]; uint32_t a_sw[2];
    #pragma unroll
    for (int mt = 0; mt < 2; mt++) {
        int rr = warpM * 32 + mt * 16 + rit;
        a_row[mt] = abase + (uint32_t)rr * 512u;
        a_sw[mt]  = (uint32_t)(rr & 7);
    }
    const uint32_t ksw = (uint32_t)(rit & 7);
    uint32_t boff[4];
    #pragma unroll
    for (int np = 0; np < 4; np++) {
        uint32_t nunit = (uint32_t)(warpN * 8 + np * 2 + koff);
        boff[np] = ((nunit ^ ksw) << 4);
    }
    const uint32_t browbase = abase + SM_W + (uint32_t)rit * 512u;

    #pragma unroll 1
    for (int c = 0; c < 8; c++) {
        if (c < 6)       { asm volatile("cp.async.wait_group 2;" ::: "memory"); }
        else if (c == 6) { asm volatile("cp.async.wait_group 1;" ::: "memory"); }
        else             { asm volatile("cp.async.wait_group 0;" ::: "memory"); }
        __syncthreads();
        if (c < 5)
            cp_chunk(WhL + (c + 3) * 16384,
                     abase + SM_W + (uint32_t)(((c + 3) & 3) * 16384), tid);
        const uint32_t bb_cur = (uint32_t)((c & 3) * 16384);
        #pragma unroll
        for (int s = 0; s < 2; s++) {
            const int k16 = c * 2 + s;
            uint32_t ah[2][4];
            #pragma unroll
            for (int mt = 0; mt < 2; mt++) {
                uint32_t unit = (uint32_t)(k16 * 2 + koff);
                ldsm_x4(ah[mt], a_row[mt] + ((unit ^ a_sw[mt]) << 4));
            }
            const uint32_t brow = browbase + bb_cur + (uint32_t)(s * 8192);
            #pragma unroll
            for (int np = 0; np < 4; np++) {
                uint32_t bh[4];
                ldsm_x4_t(bh, brow + boff[np]);
                #pragma unroll
                for (int mt = 0; mt < 2; mt++) {
                    mma_f16(acc[mt][np * 2],     ah[mt], bh[0], bh[1]);
                    mma_f16(acc[mt][np * 2 + 1], ah[mt], bh[2], bh[3]);
                }
            }
        }
    }
}

__global__ __launch_bounds__(256, 2)
void pair_mma_kernel(const float* __restrict__ b1,  const float* __restrict__ b2,
                     const float* __restrict__ b3,  const float* __restrict__ Wf,
                     const float* __restrict__ bfp, const float* __restrict__ bv1,
                     const float* __restrict__ Wv2, const float* __restrict__ bv2,
                     float* __restrict__ out)
{
    extern __shared__ char smraw[];
    const uint32_t smbase = smem_u32(smraw);
    const uint32_t abase  = (smbase + 1023u) & ~1023u;
    char* smp = smraw + (abase - smbase);
    float* qpb  = (float*)(smp + SM_VEC);
    float* vqb  = qpb + 256;
    float* b2s  = vqb + 256;
    float* b3s  = b2s + 256;
    float* wfs  = b3s + 256;
    float* wv2s = wfs + 256;
    float* red  = wv2s + 256;   // 256 floats: [row(64)][warpN(4)]
    float* vred = red + 256;    // 256 floats: [key(64)][p(4)]

    const int tid   = threadIdx.x;
    const int lane  = tid & 31;
    const int w     = tid >> 5;
    const int warpM = w & 1, warpN = w >> 1;  // 2 x 4 warp grid
    const int quad  = tid >> 6;               // 0..3
    const int m     = tid & 63;               // key within tile
    const int bid = blockIdx.x;
    const int kt  = bid & 7;
    const int q   = (bid >> 3) & 511;
    const int b   = bid >> 12;
    const int k0  = kt << 6;
    const int rowb  = b * SKK + k0 + m;
    const int lbase = (b * SQ + q) * SKK + k0;

    // prefetch W2 chunks 0..2 immediately
    cp_chunk((const char*)g_Wh,         abase + SM_W,          tid);
    cp_chunk((const char*)g_Wh + 16384, abase + SM_W + 16384u, tid);
    cp_chunk((const char*)g_Wh + 32768, abase + SM_W + 32768u, tid);

    // vectors (256 threads, one element of each vector per thread)
    {
        const int r = (b * SQ + q) * HH;
        qpb[tid]  = g_qp[r + tid] + b1[tid];
        vqb[tid]  = g_vq[r + tid] + bv1[tid];
        b2s[tid]  = b2[tid];
        b3s[tid]  = b3[tid];
        wfs[tid]  = Wf[tid];
        wv2s[tid] = Wv2[tid];
    }
    __syncthreads();

    // ---- build ALL of A (h0) + variance dot (peer CTA hides this) ----
    {
        #pragma unroll 4
        for (int gg = 0; gg < 16; gg++) {
            int g0 = gg * 2;
            int j0 = 8 * g0 + quad * 2;
            float v0 = fmaxf(qpb[j0]     + g_kpT[j0 * MR + rowb],       0.f);
            float v1 = fmaxf(qpb[j0 + 1] + g_kpT[(j0 + 1) * MR + rowb], 0.f);
            float v2 = fmaxf(qpb[j0 + 8] + g_kpT[(j0 + 8) * MR + rowb], 0.f);
            float v3 = fmaxf(qpb[j0 + 9] + g_kpT[(j0 + 9) * MR + rowb], 0.f);
            a_store_units(smp, m, quad, g0, v0, v1, v2, v3);
        }
        float vacc = 0.f;
        #pragma unroll 8
        for (int jj = 0; jj < 64; jj++) {
            int j = quad * 64 + jj;
            vacc = fmaf(fmaxf(vqb[j] + g_vkT[j * MR + rowb], 0.f), wv2s[j], vacc);
        }
        vred[m * 4 + quad] = vacc;
    }
    __syncthreads();   // A visible to all warps (W chunk0 wait happens in gemm)

    // ---- GEMM 1: D = h0 @ W2 ----
    float acc[2][8][4];
    #pragma unroll
    for (int i = 0; i < 2; i++)
        #pragma unroll
        for (int j = 0; j < 8; j++)
            #pragma unroll
            for (int e = 0; e < 4; e++) acc[i][j][e] = 0.f;
    gemm_pass(abase, (const char*)g_Wh, warpM, warpN, lane, tid, acc);
    __syncthreads();   // all W2 + h0 reads done

    // prefetch W3 chunks 0..2 (overlaps epilogue 1)
    cp_chunk((const char*)g_Wh + 131072,         abase + SM_W,          tid);
    cp_chunk((const char*)g_Wh + 131072 + 16384, abase + SM_W + 16384u, tid);
    cp_chunk((const char*)g_Wh + 131072 + 32768, abase + SM_W + 32768u, tid);

    // variance finalize
    if (tid < 64) {
        float s = vred[tid * 4] + vred[tid * 4 + 1] + vred[tid * 4 + 2] + vred[tid * 4 + 3]
                  + bv2[0];
        out[NTOT + lbase + tid] = softplusf(s);
    }

    // ---- epilogue 1: h1 = relu(D + b2) -> A buffer (fp16) ----
    {
        const int g  = lane >> 2;
        const int tg = lane & 3;
        #pragma unroll
        for (int mt = 0; mt < 2; mt++) {
            int r0 = warpM * 32 + mt * 16 + g;
            int r1 = r0 + 8;
            uint32_t row0 = (uint32_t)r0 * 512u;
            uint32_t row1 = (uint32_t)r1 * 512u;
            #pragma unroll
            for (int nt = 0; nt < 8; nt++) {
                int c0 = warpN * 64 + nt * 8 + tg * 2;
                float b20 = b2s[c0], b21 = b2s[c0 + 1];
                float v00 = fmaxf(acc[mt][nt][0] + b20, 0.f);
                float v01 = fmaxf(acc[mt][nt][1] + b21, 0.f);
                float v10 = fmaxf(acc[mt][nt][2] + b20, 0.f);
                float v11 = fmaxf(acc[mt][nt][3] + b21, 0.f);
                uint32_t unit = (uint32_t)(c0 >> 3);
                uint32_t o0 = row0 + ((unit ^ (uint32_t)(r0 & 7)) << 4) + (uint32_t)(tg * 4);
                uint32_t o1 = row1 + ((unit ^ (uint32_t)(r1 & 7)) << 4) + (uint32_t)(tg * 4);
                *(uint32_t*)(smp + SM_A + o0) = f16x2bits(v00, v01);
                *(uint32_t*)(smp + SM_A + o1) = f16x2bits(v10, v11);
            }
        }
    }
    __syncthreads();

    // ---- GEMM 2: D = h1 @ W3 ----
    #pragma unroll
    for (int i = 0; i < 2; i++)
        #pragma unroll
        for (int j = 0; j < 8; j++)
            #pragma unroll
            for (int e = 0; e < 4; e++) acc[i][j][e] = 0.f;
    gemm_pass(abase, (const char*)g_Wh + 131072, warpM, warpN, lane, tid, acc);

    // ---- epilogue 2: logit = relu(D + b3) . Wf, cross-warp reduce ----
    {
        const int g  = lane >> 2;
        const int tg = lane & 3;
        #pragma unroll
        for (int mt = 0; mt < 2; mt++) {
            float lg0 = 0.f, lg1 = 0.f;
            #pragma unroll
            for (int nt = 0; nt < 8; nt++) {
                int c0 = warpN * 64 + nt * 8 + tg * 2;
                float b30 = b3s[c0], b31 = b3s[c0 + 1];
                float w0  = wfs[c0], w1  = wfs[c0 + 1];
                lg0 = fmaf(fmaxf(acc[mt][nt][0] + b30, 0.f), w0, lg0);
                lg0 = fmaf(fmaxf(acc[mt][nt][1] + b31, 0.f), w1, lg0);
                lg1 = fmaf(fmaxf(acc[mt][nt][2] + b30, 0.f), w0, lg1);
                lg1 = fmaf(fmaxf(acc[mt][nt][3] + b31, 0.f), w1, lg1);
            }
            lg0 += __shfl_xor_sync(0xffffffffu, lg0, 1);
            lg0 += __shfl_xor_sync(0xffffffffu, lg0, 2);
            lg1 += __shfl_xor_sync(0xffffffffu, lg1, 1);
            lg1 += __shfl_xor_sync(0xffffffffu, lg1, 2);
            if (tg == 0) {
                int r0 = warpM * 32 + mt * 16 + g;
                red[r0 * 4 + warpN]       = lg0;
                red[(r0 + 8) * 4 + warpN] = lg1;
            }
        }
    }
    __syncthreads();
    if (tid < 64) {
        float s = red[tid * 4] + red[tid * 4 + 1] + red[tid * 4 + 2] + red[tid * 4 + 3]
                  + bfp[0];
        out[lbase + tid] = s;
    }
}

// ---------------- launcher -----------------------------------------------------
extern "C" void kernel_launch(void* const* d_in, const int* in_sizes, int n_in,
                              void* d_out, int out_size)
{
    const float* query = (const float*)d_in[0];
    const float* key   = (const float*)d_in[1];
    const float* Wqe   = (const float*)d_in[2];
    const float* bqe   = (const float*)d_in[3];
    const float* Wke   = (const float*)d_in[4];
    const float* bke   = (const float*)d_in[5];
    const float* W1    = (const float*)d_in[6];
    const float* b1    = (const float*)d_in[7];
    const float* W2    = (const float*)d_in[8];
    const float* b2    = (const float*)d_in[9];
    const float* W3    = (const float*)d_in[10];
    const float* b3    = (const float*)d_in[11];
    const float* Wf    = (const float*)d_in[12];
    const float* bf    = (const float*)d_in[13];
    const float* Wv1   = (const float*)d_in[14];
    const float* bv1   = (const float*)d_in[15];
    const float* Wv2   = (const float*)d_in[16];
    const float* bv2   = (const float*)d_in[17];
    float* out = (float*)d_out;

    void *p_qf, *p_kf, *p_qp, *p_vq, *p_kpT, *p_vkT;
    cudaGetSymbolAddress(&p_qf,  g_qf);
    cudaGetSymbolAddress(&p_kf,  g_kf);
    cudaGetSymbolAddress(&p_qp,  g_qp);
    cudaGetSymbolAddress(&p_vq,  g_vq);
    cudaGetSymbolAddress(&p_kpT, g_kpT);
    cudaGetSymbolAddress(&p_vkT, g_vkT);

    // weight convert (independent of projections)
    wsplit_kernel<<<256, 256>>>(W2, W3);

    // encoders: qf = relu(query@Wqe+bqe), kf = relu(key@Wke+bke)
    ProjJob e0 { query, Wqe, bqe, (float*)p_qf, 0, 1, 0 };
    ProjJob e1 { key,   Wke, bke, (float*)p_kf, 0, 1, 0 };
    proj_batch_kernel<<<dim3(4, 32, 2), 256>>>(e0, e1, e0, e0, EE);

    // stage-2 projections
    ProjJob s0 { (const float*)p_qf, W1,  nullptr, (float*)p_qp,  0,   0, 0 };
    ProjJob s1 { (const float*)p_kf, W1,  nullptr, (float*)p_kpT, 256, 0, 1 };
    ProjJob s2 { (const float*)p_qf, Wv1, nullptr, (float*)p_vq,  0,   0, 0 };
    ProjJob s3 { (const float*)p_kf, Wv1, nullptr, (float*)p_vkT, 256, 0, 1 };
    proj_batch_kernel<<<dim3(4, 32, 4), 256>>>(s0, s1, s2, s3, HH);

    // main fused pairwise-MLP kernel (fp16 mma, 2 CTAs/SM)
    cudaFuncSetAttribute(pair_mma_kernel,
                         cudaFuncAttributeMaxDynamicSharedMemorySize, SMEM_BYTES);
    pair_mma_kernel<<<BB * SQ * (SKK / 64), 256, SMEM_BYTES>>>(
        b1, b2, b3, Wf, bf, bv1, Wv2, bv2, out);
}